// round 6
// baseline (speedup 1.0000x reference)
#include <cuda_runtime.h>
#include <cuda_bf16.h>

// N = 1e6 rows, D = 128 (32 float4/row), C = 1024 classes.
// loss = mean(relu(0.1-|q|)) + mean_c var_c(q) + (mean q)^2,  q_i = sum_d J_d z_id^2
// Single kernel: streaming pass -> per-class sufficient stats (S1,S2,cnt) ->
// last-block finalize -> self-reset of all accumulators for the next replay.
#define NUM_C 1024

// Zero-initialized at module load; the finalizing block re-zeros them at the
// end of every launch, so each replay starts from zeros (deterministic).
__device__ float g_s1[NUM_C];
__device__ float g_s2[NUM_C];
__device__ float g_cnt[NUM_C];
__device__ float g_sumRelu;
__device__ float g_sumQ;
__device__ unsigned int g_ticket;

// ---------------------------------------------------------------------------
__device__ __forceinline__ float rowdot(const float4 v, const float4 j)
{
    return j.x*v.x*v.x + j.y*v.y*v.y + j.z*v.z*v.z + j.w*v.w*v.w;
}

// Load 8 consecutive rows (subgroup g of a 32-row window), lane-coalesced.
__device__ __forceinline__ void load8(float4* dst, const float4* __restrict__ z4,
                                      long long base, int g, int lane)
{
    const float4* p = z4 + (base + 8*g) * 32 + lane;
    #pragma unroll
    for (int u = 0; u < 8; u++) dst[u] = __ldcs(p + u * 32);
}

// Selection-merge reduction: 8 row-sums in 9 SHFLs. After it, lane l holds the
// full sum of local row (l>>2); deposit into myq for lanes with (l&3)==g, so
// lane l ultimately owns global row base + 8*(l&3) + (l>>2).
__device__ __forceinline__ void reduce8(const float4* v, const float4 j,
                                        int lane, int g, float& myq)
{
    float m[8];
    #pragma unroll
    for (int u = 0; u < 8; u++) m[u] = rowdot(v[u], j);

    const bool b4 = (lane & 16) != 0;
    const bool b3 = (lane &  8) != 0;
    const bool b2 = (lane &  4) != 0;

    float w[4];
    #pragma unroll
    for (int u = 0; u < 4; u++) {
        float s = b4 ? m[u+4] : m[u];
        float r = b4 ? m[u]   : m[u+4];
        w[u] = s + __shfl_xor_sync(0xffffffffu, r, 16);
    }
    float x[2];
    #pragma unroll
    for (int u = 0; u < 2; u++) {
        float s = b3 ? w[u+2] : w[u];
        float r = b3 ? w[u]   : w[u+2];
        x[u] = s + __shfl_xor_sync(0xffffffffu, r, 8);
    }
    float s = b2 ? x[1] : x[0];
    float r = b2 ? x[0] : x[1];
    float t = s + __shfl_xor_sync(0xffffffffu, r, 4);
    t += __shfl_xor_sync(0xffffffffu, t, 2);
    t += __shfl_xor_sync(0xffffffffu, t, 1);

    if ((lane & 3) == g) myq = t;
}

// ---------------------------------------------------------------------------
__global__ __launch_bounds__(256, 2)
void k_main(const float4* __restrict__ z4,
            const void*   __restrict__ labels,
            const float4* __restrict__ J4,
            float* __restrict__ out,
            int N)
{
    __shared__ float s1[NUM_C], s2[NUM_C], scnt[NUM_C];
    __shared__ float wR[8], wQ[8];
    __shared__ int   sLab64;
    __shared__ int   sLast;

    const int tid = threadIdx.x;
    for (int i = tid; i < NUM_C; i += blockDim.x) { s1[i]=0.f; s2[i]=0.f; scnt[i]=0.f; }
    if (tid == 0) {
        // int64 labels => every odd 32-bit word of the first 32 labels is 0.
        // int32 labels => odd words are random labels; P(all 32 zero) ~ 1024^-32.
        const unsigned int* lw = (const unsigned int*)labels;
        unsigned int o = 0;
        #pragma unroll
        for (int k = 0; k < 32; k++) o |= lw[2*k + 1];
        sLab64 = (o == 0u);
    }
    __syncthreads();

    const bool l64 = (sLab64 != 0);
    const long long* __restrict__ lab64 = (const long long*)labels;
    const int*       __restrict__ lab32 = (const int*)labels;

    const int lane = tid & 31;
    const int warp = tid >> 5;
    const int wpb  = blockDim.x >> 5;
    const long long gw = (long long)blockIdx.x * wpb + warp;
    const long long nw = (long long)gridDim.x * wpb;

    const float4 j = J4[lane];

    float accR = 0.f, accQ = 0.f;
    float4 va[8], vb[8];

    long long base   = gw * 32;
    const long long stride = nw * 32;

    if (base + 32 <= (long long)N) load8(va, z4, base, 0, lane);

    while (base + 32 <= (long long)N) {
        const long long nbase = base + stride;
        float myq = 0.f;

        load8(vb, z4, base, 1, lane);
        reduce8(va, j, lane, 0, myq);
        load8(va, z4, base, 2, lane);
        reduce8(vb, j, lane, 1, myq);
        load8(vb, z4, base, 3, lane);
        reduce8(va, j, lane, 2, myq);
        if (nbase + 32 <= (long long)N) load8(va, z4, nbase, 0, lane);  // next-iter prefetch
        reduce8(vb, j, lane, 3, myq);

        // Bookkeeping: every lane owns one distinct row of this 32-row window.
        {
            const long long row = base + 8 * (lane & 3) + (lane >> 2);
            const int c = l64 ? (int)lab64[row] : lab32[row];
            atomicAdd(&s1[c],   myq);
            atomicAdd(&s2[c],   myq * myq);
            atomicAdd(&scnt[c], 1.f);
            accQ += myq;
            float rr = 0.1f - fabsf(myq);
            accR += (rr > 0.f) ? rr : 0.f;
        }
        base = nbase;
    }

    // Tail (only if N % 32 != 0): leftover rows, one row per warp-pass.
    if (base < (long long)N) {
        for (long long row = base; row < (long long)N; row++) {
            float4 v = __ldcs(z4 + row * 32 + lane);
            float p = rowdot(v, j);
            #pragma unroll
            for (int off = 16; off; off >>= 1)
                p += __shfl_xor_sync(0xffffffffu, p, off);
            if (lane == 0) {
                const int c = l64 ? (int)lab64[row] : lab32[row];
                atomicAdd(&s1[c],   p);
                atomicAdd(&s2[c],   p * p);
                atomicAdd(&scnt[c], 1.f);
                accQ += p;
                float rr = 0.1f - fabsf(p);
                accR += (rr > 0.f) ? rr : 0.f;
            }
        }
    }

    // Scalar sums: warp reduce, then block reduce.
    #pragma unroll
    for (int off = 16; off; off >>= 1) {
        accR += __shfl_xor_sync(0xffffffffu, accR, off);
        accQ += __shfl_xor_sync(0xffffffffu, accQ, off);
    }
    if (lane == 0) { wR[warp] = accR; wQ[warp] = accQ; }
    __syncthreads();

    // Flush class bins (skip untouched).
    for (int i = tid; i < NUM_C; i += blockDim.x) {
        float c = scnt[i];
        if (c != 0.f) {
            atomicAdd(&g_s1[i],  s1[i]);
            atomicAdd(&g_s2[i],  s2[i]);
            atomicAdd(&g_cnt[i], c);
        }
    }
    if (tid == 0) {
        float r = 0.f, qq = 0.f;
        for (int w = 0; w < wpb; w++) { r += wR[w]; qq += wQ[w]; }
        atomicAdd(&g_sumRelu, r);
        atomicAdd(&g_sumQ,    qq);
    }

    // ------- last-block finalize (threadfence-ticket pattern) -------
    __threadfence();
    __syncthreads();
    if (tid == 0) {
        unsigned int old = atomicAdd(&g_ticket, 1u);
        sLast = (old == gridDim.x - 1u);
    }
    __syncthreads();
    if (!sLast) return;

    __threadfence();   // acquire: see all blocks' accumulations

    // var_c = (S2 - S1^2/cnt)/cnt with cnt clipped at 1 (empty class -> 0).
    // 256 threads x 4 classes each; __ldcg = read via L2 (atomics landed there).
    float varAcc = 0.f;
    #pragma unroll
    for (int k = 0; k < NUM_C / 256; k++) {
        int c = tid + k * 256;
        float cnt = __ldcg(&g_cnt[c]);
        float cc  = fmaxf(cnt, 1.f);
        float a   = __ldcg(&g_s1[c]);
        float b   = __ldcg(&g_s2[c]);
        varAcc += (b - a * a / cc) / cc;
    }
    #pragma unroll
    for (int off = 16; off; off >>= 1)
        varAcc += __shfl_xor_sync(0xffffffffu, varAcc, off);
    if (lane == 0) wR[warp] = varAcc;
    __syncthreads();
    if (tid == 0) {
        float v = 0.f;
        for (int w = 0; w < wpb; w++) v += wR[w];
        float invN = 1.f / (float)N;
        float lc = __ldcg(&g_sumRelu) * invN;
        float mq = __ldcg(&g_sumQ) * invN;
        out[0] = lc + v * (1.f / (float)NUM_C) + mq * mq;
    }
    __syncthreads();

    // Self-reset for the next replay (globals start zeroed at module load).
    for (int i = tid; i < NUM_C; i += blockDim.x) {
        g_s1[i] = 0.f; g_s2[i] = 0.f; g_cnt[i] = 0.f;
    }
    if (tid == 0) {
        g_sumRelu = 0.f;
        g_sumQ    = 0.f;
        __threadfence();
        g_ticket  = 0u;
    }
}

// ---------------------------------------------------------------------------
extern "C" void kernel_launch(void* const* d_in, const int* in_sizes, int n_in,
                              void* d_out, int out_size)
{
    const float4* z4     = (const float4*)d_in[0];
    const void*   labels = d_in[1];
    const float4* J4     = (const float4*)d_in[2];
    const int N = in_sizes[1];

    // GB300 has 152 SMs; 2 blocks/SM (launch_bounds) -> 304 resident blocks.
    k_main<<<304, 256>>>(z4, labels, J4, (float*)d_out, N);
}

// round 8
// speedup vs baseline: 1.0982x; 1.0982x over previous
#include <cuda_runtime.h>
#include <cuda_bf16.h>

// N = 1e6 rows, D = 128 (32 float4/row), C = 1024 classes.
// loss = mean(relu(0.1-|q|)) + mean_c var_c(q) + (mean q)^2,  q_i = sum_d J_d z_id^2
// Two kernels: (1) streaming pass -> per-class sufficient stats (S1,S2,cnt);
// (2) finalize + self-reset of accumulators for the next graph replay.
#define NUM_C 1024

// Zero-initialized at module load; k_finalize re-zeros them at the end of
// every launch, so each replay starts from zeros (deterministic).
__device__ float g_s1[NUM_C];
__device__ float g_s2[NUM_C];
__device__ float g_cnt[NUM_C];
__device__ float g_sumRelu;
__device__ float g_sumQ;

// ---------------------------------------------------------------------------
__device__ __forceinline__ float rowdot(const float4 v, const float4 j)
{
    return j.x*v.x*v.x + j.y*v.y*v.y + j.z*v.z*v.z + j.w*v.w*v.w;
}

// Load 8 consecutive rows (subgroup g of a 32-row window), lane-coalesced.
__device__ __forceinline__ void load8(float4* dst, const float4* __restrict__ z4,
                                      long long base, int g, int lane)
{
    const float4* p = z4 + (base + 8*g) * 32 + lane;
    #pragma unroll
    for (int u = 0; u < 8; u++) dst[u] = __ldcs(p + u * 32);
}

// Selection-merge reduction: 8 row-sums in 9 SHFLs. After it, lane l holds the
// full sum of local row (l>>2); deposit into myq for lanes with (l&3)==g, so
// lane l ultimately owns global row base + 8*(l&3) + (l>>2).
__device__ __forceinline__ void reduce8(const float4* v, const float4 j,
                                        int lane, int g, float& myq)
{
    float m[8];
    #pragma unroll
    for (int u = 0; u < 8; u++) m[u] = rowdot(v[u], j);

    const bool b4 = (lane & 16) != 0;
    const bool b3 = (lane &  8) != 0;
    const bool b2 = (lane &  4) != 0;

    float w[4];
    #pragma unroll
    for (int u = 0; u < 4; u++) {
        float s = b4 ? m[u+4] : m[u];
        float r = b4 ? m[u]   : m[u+4];
        w[u] = s + __shfl_xor_sync(0xffffffffu, r, 16);
    }
    float x[2];
    #pragma unroll
    for (int u = 0; u < 2; u++) {
        float s = b3 ? w[u+2] : w[u];
        float r = b3 ? w[u]   : w[u+2];
        x[u] = s + __shfl_xor_sync(0xffffffffu, r, 8);
    }
    float s = b2 ? x[1] : x[0];
    float r = b2 ? x[0] : x[1];
    float t = s + __shfl_xor_sync(0xffffffffu, r, 4);
    t += __shfl_xor_sync(0xffffffffu, t, 2);
    t += __shfl_xor_sync(0xffffffffu, t, 1);

    if ((lane & 3) == g) myq = t;
}

// ---------------------------------------------------------------------------
__global__ __launch_bounds__(256, 2)
void k_main(const float4* __restrict__ z4,
            const void*   __restrict__ labels,
            const float4* __restrict__ J4,
            int N)
{
    __shared__ float s1[NUM_C], s2[NUM_C], scnt[NUM_C];
    __shared__ float wR[8], wQ[8];
    __shared__ int   sLab64;

    const int tid = threadIdx.x;
    for (int i = tid; i < NUM_C; i += blockDim.x) { s1[i]=0.f; s2[i]=0.f; scnt[i]=0.f; }
    if (tid == 0) {
        // int64 labels => every odd 32-bit word of the first 32 labels is 0.
        // int32 labels => odd words are random labels; P(all 32 zero) ~ 1024^-32.
        const unsigned int* lw = (const unsigned int*)labels;
        unsigned int o = 0;
        #pragma unroll
        for (int k = 0; k < 32; k++) o |= lw[2*k + 1];
        sLab64 = (o == 0u);
    }
    __syncthreads();

    const bool l64 = (sLab64 != 0);
    const long long* __restrict__ lab64 = (const long long*)labels;
    const int*       __restrict__ lab32 = (const int*)labels;

    const int lane = tid & 31;
    const int warp = tid >> 5;
    const int wpb  = blockDim.x >> 5;
    const long long gw = (long long)blockIdx.x * wpb + warp;
    const long long nw = (long long)gridDim.x * wpb;

    const float4 j = J4[lane];

    float accR = 0.f, accQ = 0.f;
    float4 va[8], vb[8];

    long long base   = gw * 32;
    const long long stride = nw * 32;

    if (base + 32 <= (long long)N) load8(va, z4, base, 0, lane);

    while (base + 32 <= (long long)N) {
        const long long nbase = base + stride;
        float myq = 0.f;

        load8(vb, z4, base, 1, lane);
        reduce8(va, j, lane, 0, myq);
        load8(va, z4, base, 2, lane);
        reduce8(vb, j, lane, 1, myq);
        load8(vb, z4, base, 3, lane);
        reduce8(va, j, lane, 2, myq);
        if (nbase + 32 <= (long long)N) load8(va, z4, nbase, 0, lane);  // next-iter prefetch
        reduce8(vb, j, lane, 3, myq);

        // Bookkeeping: every lane owns one distinct row of this 32-row window.
        {
            const long long row = base + 8 * (lane & 3) + (lane >> 2);
            const int c = l64 ? (int)lab64[row] : lab32[row];
            atomicAdd(&s1[c],   myq);
            atomicAdd(&s2[c],   myq * myq);
            atomicAdd(&scnt[c], 1.f);
            accQ += myq;
            float rr = 0.1f - fabsf(myq);
            accR += (rr > 0.f) ? rr : 0.f;
        }
        base = nbase;
    }

    // Tail (only if N % 32 != 0): leftover rows, one row per warp-pass.
    if (base < (long long)N) {
        for (long long row = base; row < (long long)N; row++) {
            float4 v = __ldcs(z4 + row * 32 + lane);
            float p = rowdot(v, j);
            #pragma unroll
            for (int off = 16; off; off >>= 1)
                p += __shfl_xor_sync(0xffffffffu, p, off);
            if (lane == 0) {
                const int c = l64 ? (int)lab64[row] : lab32[row];
                atomicAdd(&s1[c],   p);
                atomicAdd(&s2[c],   p * p);
                atomicAdd(&scnt[c], 1.f);
                accQ += p;
                float rr = 0.1f - fabsf(p);
                accR += (rr > 0.f) ? rr : 0.f;
            }
        }
    }

    // Scalar sums: warp reduce, then block reduce.
    #pragma unroll
    for (int off = 16; off; off >>= 1) {
        accR += __shfl_xor_sync(0xffffffffu, accR, off);
        accQ += __shfl_xor_sync(0xffffffffu, accQ, off);
    }
    if (lane == 0) { wR[warp] = accR; wQ[warp] = accQ; }
    __syncthreads();

    // Flush class bins (skip untouched).
    for (int i = tid; i < NUM_C; i += blockDim.x) {
        float c = scnt[i];
        if (c != 0.f) {
            atomicAdd(&g_s1[i],  s1[i]);
            atomicAdd(&g_s2[i],  s2[i]);
            atomicAdd(&g_cnt[i], c);
        }
    }
    if (tid == 0) {
        float r = 0.f, qq = 0.f;
        for (int w = 0; w < wpb; w++) { r += wR[w]; qq += wQ[w]; }
        atomicAdd(&g_sumRelu, r);
        atomicAdd(&g_sumQ,    qq);
    }
}

// ---------------------------------------------------------------------------
// var_c = (S2 - S1^2/cnt)/cnt with cnt clipped at 1 (empty class -> 0).
// Also self-resets all accumulators so the next replay starts from zeros.
__global__ void k_finalize(float* __restrict__ out, int N)
{
    __shared__ float red[32];
    int c = threadIdx.x;
    float cnt = g_cnt[c];
    float cc  = fmaxf(cnt, 1.f);
    float a   = g_s1[c];
    float b   = g_s2[c];
    float var = (b - a * a / cc) / cc;

    #pragma unroll
    for (int off = 16; off; off >>= 1)
        var += __shfl_xor_sync(0xffffffffu, var, off);
    if ((c & 31) == 0) red[c >> 5] = var;
    __syncthreads();
    if (c < 32) {
        float v = red[c];
        #pragma unroll
        for (int off = 16; off; off >>= 1)
            v += __shfl_xor_sync(0xffffffffu, v, off);
        if (c == 0) {
            float invN = 1.f / (float)N;
            float lc = g_sumRelu * invN;
            float mq = g_sumQ * invN;
            out[0] = lc + v * (1.f / (float)NUM_C) + mq * mq;
        }
    }

    // Reset for the next replay (all 1024 threads, after the reads above).
    __syncthreads();
    g_s1[c] = 0.f; g_s2[c] = 0.f; g_cnt[c] = 0.f;
    if (c == 0) { g_sumRelu = 0.f; g_sumQ = 0.f; }
}

// ---------------------------------------------------------------------------
extern "C" void kernel_launch(void* const* d_in, const int* in_sizes, int n_in,
                              void* d_out, int out_size)
{
    const float4* z4     = (const float4*)d_in[0];
    const void*   labels = d_in[1];
    const float4* J4     = (const float4*)d_in[2];
    const int N = in_sizes[1];

    // 2 blocks/SM (launch_bounds), grid-stride over 32-row windows.
    k_main<<<296, 256>>>(z4, labels, J4, N);
    k_finalize<<<1, NUM_C>>>((float*)d_out, N);
}

// round 9
// speedup vs baseline: 1.1050x; 1.0061x over previous
#include <cuda_runtime.h>
#include <cuda_bf16.h>

// N = 1e6 rows, D = 128 (32 float4/row), C = 1024 classes.
// loss = mean(relu(0.1-|q|)) + mean_c var_c(q) + (mean q)^2,  q_i = sum_d J_d z_id^2
// Two kernels: (1) streaming pass -> per-class sufficient stats (S1,S2,cnt);
// (2) finalize (PDL-overlapped launch) + self-reset of accumulators.
#define NUM_C 1024

// Zero-initialized at module load; k_finalize re-zeros them at the end of
// every launch, so each replay starts from zeros (deterministic).
__device__ float g_s1[NUM_C];
__device__ float g_s2[NUM_C];
__device__ float g_cnt[NUM_C];
__device__ float g_sumRelu;
__device__ float g_sumQ;

// ---------------------------------------------------------------------------
__device__ __forceinline__ float rowdot(const float4 v, const float4 j)
{
    return j.x*v.x*v.x + j.y*v.y*v.y + j.z*v.z*v.z + j.w*v.w*v.w;
}

// Load 8 consecutive rows (subgroup g of a 32-row window), lane-coalesced.
__device__ __forceinline__ void load8(float4* dst, const float4* __restrict__ z4,
                                      long long base, int g, int lane)
{
    const float4* p = z4 + (base + 8*g) * 32 + lane;
    #pragma unroll
    for (int u = 0; u < 8; u++) dst[u] = __ldcs(p + u * 32);
}

// Selection-merge reduction: 8 row-sums in 9 SHFLs. After it, lane l holds the
// full sum of local row (l>>2); deposit into myq for lanes with (l&3)==g, so
// lane l ultimately owns global row base + 8*(l&3) + (l>>2).
__device__ __forceinline__ void reduce8(const float4* v, const float4 j,
                                        int lane, int g, float& myq)
{
    float m[8];
    #pragma unroll
    for (int u = 0; u < 8; u++) m[u] = rowdot(v[u], j);

    const bool b4 = (lane & 16) != 0;
    const bool b3 = (lane &  8) != 0;
    const bool b2 = (lane &  4) != 0;

    float w[4];
    #pragma unroll
    for (int u = 0; u < 4; u++) {
        float s = b4 ? m[u+4] : m[u];
        float r = b4 ? m[u]   : m[u+4];
        w[u] = s + __shfl_xor_sync(0xffffffffu, r, 16);
    }
    float x[2];
    #pragma unroll
    for (int u = 0; u < 2; u++) {
        float s = b3 ? w[u+2] : w[u];
        float r = b3 ? w[u]   : w[u+2];
        x[u] = s + __shfl_xor_sync(0xffffffffu, r, 8);
    }
    float s = b2 ? x[1] : x[0];
    float r = b2 ? x[0] : x[1];
    float t = s + __shfl_xor_sync(0xffffffffu, r, 4);
    t += __shfl_xor_sync(0xffffffffu, t, 2);
    t += __shfl_xor_sync(0xffffffffu, t, 1);

    if ((lane & 3) == g) myq = t;
}

// ---------------------------------------------------------------------------
__global__ __launch_bounds__(256, 2)
void k_main(const float4* __restrict__ z4,
            const void*   __restrict__ labels,
            const float4* __restrict__ J4,
            int N)
{
    __shared__ float s1[NUM_C], s2[NUM_C], scnt[NUM_C];
    __shared__ float wR[8], wQ[8];
    __shared__ int   sLab64;

    const int tid = threadIdx.x;
    for (int i = tid; i < NUM_C; i += blockDim.x) { s1[i]=0.f; s2[i]=0.f; scnt[i]=0.f; }
    if (tid == 0) {
        // int64 labels => every odd 32-bit word of the first 32 labels is 0.
        // int32 labels => odd words are random labels; P(all 32 zero) ~ 1024^-32.
        const unsigned int* lw = (const unsigned int*)labels;
        unsigned int o = 0;
        #pragma unroll
        for (int k = 0; k < 32; k++) o |= lw[2*k + 1];
        sLab64 = (o == 0u);
    }
    __syncthreads();

    // Label index stride: int64 labels -> read only the low 32-bit word
    // (values < 1024 fit; halves label bandwidth vs 64-bit loads).
    const int lstep = (sLab64 != 0) ? 2 : 1;
    const int* __restrict__ lab32 = (const int*)labels;

    const int lane = tid & 31;
    const int warp = tid >> 5;
    const int wpb  = blockDim.x >> 5;
    const long long gw = (long long)blockIdx.x * wpb + warp;
    const long long nw = (long long)gridDim.x * wpb;

    const float4 j = J4[lane];

    float accR = 0.f, accQ = 0.f;
    float4 va[8], vb[8];

    long long base   = gw * 32;
    const long long stride = nw * 32;

    // Per-window row owned by this lane: base + 8*(lane&3) + (lane>>2)
    const long long rowOfs = 8 * (lane & 3) + (lane >> 2);

    if (base + 32 <= (long long)N) load8(va, z4, base, 0, lane);

    while (base + 32 <= (long long)N) {
        const long long nbase = base + stride;
        float myq = 0.f;

        // Prefetch this window's label early: its DRAM latency hides behind
        // the 4 reduce stages instead of stalling the smem atomics.
        const int c = lab32[(base + rowOfs) * lstep];

        load8(vb, z4, base, 1, lane);
        reduce8(va, j, lane, 0, myq);
        load8(va, z4, base, 2, lane);
        reduce8(vb, j, lane, 1, myq);
        load8(vb, z4, base, 3, lane);
        reduce8(va, j, lane, 2, myq);
        if (nbase + 32 <= (long long)N) load8(va, z4, nbase, 0, lane);  // next-iter prefetch
        reduce8(vb, j, lane, 3, myq);

        // Bookkeeping: every lane owns one distinct row of this 32-row window.
        atomicAdd(&s1[c],   myq);
        atomicAdd(&s2[c],   myq * myq);
        atomicAdd(&scnt[c], 1.f);
        accQ += myq;
        float rr = 0.1f - fabsf(myq);
        accR += (rr > 0.f) ? rr : 0.f;

        base = nbase;
    }

    // Tail (only if N % 32 != 0): leftover rows, one row per warp-pass.
    if (base < (long long)N) {
        for (long long row = base; row < (long long)N; row++) {
            float4 v = __ldcs(z4 + row * 32 + lane);
            float p = rowdot(v, j);
            #pragma unroll
            for (int off = 16; off; off >>= 1)
                p += __shfl_xor_sync(0xffffffffu, p, off);
            if (lane == 0) {
                const int c = lab32[row * lstep];
                atomicAdd(&s1[c],   p);
                atomicAdd(&s2[c],   p * p);
                atomicAdd(&scnt[c], 1.f);
                accQ += p;
                float rr = 0.1f - fabsf(p);
                accR += (rr > 0.f) ? rr : 0.f;
            }
        }
    }

    // Scalar sums: warp reduce, then block reduce.
    #pragma unroll
    for (int off = 16; off; off >>= 1) {
        accR += __shfl_xor_sync(0xffffffffu, accR, off);
        accQ += __shfl_xor_sync(0xffffffffu, accQ, off);
    }
    if (lane == 0) { wR[warp] = accR; wQ[warp] = accQ; }
    __syncthreads();

    // Flush class bins (skip untouched).
    for (int i = tid; i < NUM_C; i += blockDim.x) {
        float c = scnt[i];
        if (c != 0.f) {
            atomicAdd(&g_s1[i],  s1[i]);
            atomicAdd(&g_s2[i],  s2[i]);
            atomicAdd(&g_cnt[i], c);
        }
    }
    if (tid == 0) {
        float r = 0.f, qq = 0.f;
        for (int w = 0; w < wpb; w++) { r += wR[w]; qq += wQ[w]; }
        atomicAdd(&g_sumRelu, r);
        atomicAdd(&g_sumQ,    qq);
    }
}

// ---------------------------------------------------------------------------
// var_c = (S2 - S1^2/cnt)/cnt with cnt clipped at 1 (empty class -> 0).
// Launched with programmatic stream serialization (PDL): the grid becomes
// resident while k_main drains; cudaGridDependencySynchronize() blocks until
// k_main fully completes (full memory visibility — no early trigger is used).
// Also self-resets all accumulators so the next replay starts from zeros.
__global__ void k_finalize(float* __restrict__ out, int N)
{
    cudaGridDependencySynchronize();

    __shared__ float red[32];
    int c = threadIdx.x;
    float cnt = g_cnt[c];
    float cc  = fmaxf(cnt, 1.f);
    float a   = g_s1[c];
    float b   = g_s2[c];
    float var = (b - a * a / cc) / cc;

    #pragma unroll
    for (int off = 16; off; off >>= 1)
        var += __shfl_xor_sync(0xffffffffu, var, off);
    if ((c & 31) == 0) red[c >> 5] = var;
    __syncthreads();
    if (c < 32) {
        float v = red[c];
        #pragma unroll
        for (int off = 16; off; off >>= 1)
            v += __shfl_xor_sync(0xffffffffu, v, off);
        if (c == 0) {
            float invN = 1.f / (float)N;
            float lc = g_sumRelu * invN;
            float mq = g_sumQ * invN;
            out[0] = lc + v * (1.f / (float)NUM_C) + mq * mq;
        }
    }

    // Reset for the next replay (all 1024 threads, after the reads above).
    __syncthreads();
    g_s1[c] = 0.f; g_s2[c] = 0.f; g_cnt[c] = 0.f;
    if (c == 0) { g_sumRelu = 0.f; g_sumQ = 0.f; }
}

// ---------------------------------------------------------------------------
extern "C" void kernel_launch(void* const* d_in, const int* in_sizes, int n_in,
                              void* d_out, int out_size)
{
    const float4* z4     = (const float4*)d_in[0];
    const void*   labels = d_in[1];
    const float4* J4     = (const float4*)d_in[2];
    const int N = in_sizes[1];

    // GB300: 152 SMs x 2 blocks/SM (launch_bounds) = 304 resident blocks.
    k_main<<<304, 256>>>(z4, labels, J4, N);

    // PDL launch of the finalize kernel: overlaps its launch latency with
    // k_main's tail; gridDependencySynchronize provides the ordering.
    cudaLaunchConfig_t cfg = {};
    cfg.gridDim  = dim3(1, 1, 1);
    cfg.blockDim = dim3(NUM_C, 1, 1);
    cfg.dynamicSmemBytes = 0;
    cfg.stream = 0;
    cudaLaunchAttribute attr[1];
    attr[0].id = cudaLaunchAttributeProgrammaticStreamSerialization;
    attr[0].val.programmaticStreamSerializationAllowed = 1;
    cfg.attrs = attr;
    cfg.numAttrs = 1;
    cudaLaunchKernelEx(&cfg, k_finalize, (float*)d_out, N);
}

// round 13
// speedup vs baseline: 1.1781x; 1.0662x over previous
#include <cuda_runtime.h>
#include <cuda_bf16.h>

// N = 1e6 rows, D = 128 (32 float4/row), C = 1024 classes.
// loss = mean(relu(0.1-|q|)) + mean_c var_c(q) + (mean q)^2,  q_i = sum_d J_d z_id^2
// Two kernels: (1) streaming pass -> per-class sufficient stats (S1,S2,cnt);
// (2) finalize (PDL-overlapped launch) + self-reset of accumulators.
#define NUM_C 1024

// Zero-initialized at module load; k_finalize re-zeros them at the end of
// every launch, so each replay starts from zeros (deterministic).
__device__ float g_s1[NUM_C];
__device__ float g_s2[NUM_C];
__device__ float g_cnt[NUM_C];
__device__ float g_sumRelu;
__device__ float g_sumQ;

// ---------------------------------------------------------------------------
__device__ __forceinline__ float rowdot(const float4 v, const float4 j)
{
    return j.x*v.x*v.x + j.y*v.y*v.y + j.z*v.z*v.z + j.w*v.w*v.w;
}

// Load 4 consecutive rows (subgroup g of a 32-row window), lane-coalesced.
__device__ __forceinline__ void load4(float4* dst, const float4* __restrict__ z4,
                                      int base, int g, int lane)
{
    const float4* p = z4 + (size_t)(base + 4*g) * 32 + lane;
    #pragma unroll
    for (int u = 0; u < 4; u++) dst[u] = __ldcs(p + u * 32);
}

// Selection-merge reduction: 4 row-sums in 6 SHFLs. Lane bits {16,8} select
// the row: after the two merge levels + 3-level butterfly, lane l holds the
// full sum of local row (l>>3)&3. Deposit into myq for lanes with (l&7)==g,
// so lane l ultimately owns global row base + 4*(l&7) + (l>>3).
__device__ __forceinline__ void reduce4(const float4* v, const float4 j,
                                        int lane, int g, float& myq)
{
    float m[4];
    #pragma unroll
    for (int u = 0; u < 4; u++) m[u] = rowdot(v[u], j);

    const bool b4 = (lane & 16) != 0;
    const bool b3 = (lane &  8) != 0;

    float w[2];
    #pragma unroll
    for (int u = 0; u < 2; u++) {
        float s = b4 ? m[u+2] : m[u];
        float r = b4 ? m[u]   : m[u+2];
        w[u] = s + __shfl_xor_sync(0xffffffffu, r, 16);
    }
    float s = b3 ? w[1] : w[0];
    float r = b3 ? w[0] : w[1];
    float t = s + __shfl_xor_sync(0xffffffffu, r, 8);
    t += __shfl_xor_sync(0xffffffffu, t, 4);
    t += __shfl_xor_sync(0xffffffffu, t, 2);
    t += __shfl_xor_sync(0xffffffffu, t, 1);

    if ((lane & 7) == g) myq = t;
}

// ---------------------------------------------------------------------------
__global__ __launch_bounds__(256, 3)
void k_main(const float4* __restrict__ z4,
            const void*   __restrict__ labels,
            const float4* __restrict__ J4,
            int N)
{
    __shared__ float s1[NUM_C], s2[NUM_C], scnt[NUM_C];
    __shared__ float wR[8], wQ[8];
    __shared__ int   sLab64;

    const int tid = threadIdx.x;
    for (int i = tid; i < NUM_C; i += blockDim.x) { s1[i]=0.f; s2[i]=0.f; scnt[i]=0.f; }
    if (tid == 0) {
        // int64 labels => every odd 32-bit word of the first 32 labels is 0.
        // int32 labels => odd words are random labels; P(all 32 zero) ~ 1024^-32.
        const unsigned int* lw = (const unsigned int*)labels;
        unsigned int o = 0;
        #pragma unroll
        for (int k = 0; k < 32; k++) o |= lw[2*k + 1];
        sLab64 = (o == 0u);
    }
    __syncthreads();

    // int64 labels -> read only the low 32-bit word (values < 1024 fit).
    const int lstep = (sLab64 != 0) ? 2 : 1;
    const int* __restrict__ lab32 = (const int*)labels;

    const int lane = tid & 31;
    const int warp = tid >> 5;
    const int wpb  = blockDim.x >> 5;
    const int gw = blockIdx.x * wpb + warp;
    const int nw = gridDim.x * wpb;

    const float4 j = J4[lane];

    float accR = 0.f, accQ = 0.f;
    float4 va[4], vb[4];

    int base = gw * 32;
    const int stride = nw * 32;

    // Per-window row owned by this lane.
    const int rowOfs = 4 * (lane & 7) + (lane >> 3);

    if (base + 32 <= N) load4(va, z4, base, 0, lane);

    while (base + 32 <= N) {
        const int nbase = base + stride;
        float myq = 0.f;

        // Prefetch this window's label early: its DRAM latency hides behind
        // the 8 reduce stages instead of stalling the smem atomics.
        const int c = lab32[(base + rowOfs) * lstep];

        load4(vb, z4, base, 1, lane);
        reduce4(va, j, lane, 0, myq);
        load4(va, z4, base, 2, lane);
        reduce4(vb, j, lane, 1, myq);
        load4(vb, z4, base, 3, lane);
        reduce4(va, j, lane, 2, myq);
        load4(va, z4, base, 4, lane);
        reduce4(vb, j, lane, 3, myq);
        load4(vb, z4, base, 5, lane);
        reduce4(va, j, lane, 4, myq);
        load4(va, z4, base, 6, lane);
        reduce4(vb, j, lane, 5, myq);
        load4(vb, z4, base, 7, lane);
        reduce4(va, j, lane, 6, myq);
        if (nbase + 32 <= N) load4(va, z4, nbase, 0, lane);  // next-iter prefetch
        reduce4(vb, j, lane, 7, myq);

        // Bookkeeping: every lane owns one distinct row of this 32-row window.
        atomicAdd(&s1[c],   myq);
        atomicAdd(&s2[c],   myq * myq);
        atomicAdd(&scnt[c], 1.f);
        accQ += myq;
        float rr = 0.1f - fabsf(myq);
        accR += (rr > 0.f) ? rr : 0.f;

        base = nbase;
    }

    // Tail (only if N % 32 != 0): leftover rows, one row per warp-pass.
    if (base < N) {
        for (int row = base; row < N; row++) {
            float4 v = __ldcs(z4 + (size_t)row * 32 + lane);
            float p = rowdot(v, j);
            #pragma unroll
            for (int off = 16; off; off >>= 1)
                p += __shfl_xor_sync(0xffffffffu, p, off);
            if (lane == 0) {
                const int c = lab32[row * lstep];
                atomicAdd(&s1[c],   p);
                atomicAdd(&s2[c],   p * p);
                atomicAdd(&scnt[c], 1.f);
                accQ += p;
                float rr = 0.1f - fabsf(p);
                accR += (rr > 0.f) ? rr : 0.f;
            }
        }
    }

    // Scalar sums: warp reduce, then block reduce.
    #pragma unroll
    for (int off = 16; off; off >>= 1) {
        accR += __shfl_xor_sync(0xffffffffu, accR, off);
        accQ += __shfl_xor_sync(0xffffffffu, accQ, off);
    }
    if (lane == 0) { wR[warp] = accR; wQ[warp] = accQ; }
    __syncthreads();

    // Flush class bins (skip untouched).
    for (int i = tid; i < NUM_C; i += blockDim.x) {
        float c = scnt[i];
        if (c != 0.f) {
            atomicAdd(&g_s1[i],  s1[i]);
            atomicAdd(&g_s2[i],  s2[i]);
            atomicAdd(&g_cnt[i], c);
        }
    }
    if (tid == 0) {
        float r = 0.f, qq = 0.f;
        for (int w = 0; w < wpb; w++) { r += wR[w]; qq += wQ[w]; }
        atomicAdd(&g_sumRelu, r);
        atomicAdd(&g_sumQ,    qq);
    }
}

// ---------------------------------------------------------------------------
// var_c = (S2 - S1^2/cnt)/cnt with cnt clipped at 1 (empty class -> 0).
// PDL launch: the grid becomes resident while k_main drains;
// cudaGridDependencySynchronize() blocks until k_main fully completes.
// Also self-resets all accumulators so the next replay starts from zeros.
__global__ void k_finalize(float* __restrict__ out, int N)
{
    cudaGridDependencySynchronize();

    __shared__ float red[32];
    int c = threadIdx.x;
    float cnt = g_cnt[c];
    float cc  = fmaxf(cnt, 1.f);
    float a   = g_s1[c];
    float b   = g_s2[c];
    float var = (b - a * a / cc) / cc;

    #pragma unroll
    for (int off = 16; off; off >>= 1)
        var += __shfl_xor_sync(0xffffffffu, var, off);
    if ((c & 31) == 0) red[c >> 5] = var;
    __syncthreads();
    if (c < 32) {
        float v = red[c];
        #pragma unroll
        for (int off = 16; off; off >>= 1)
            v += __shfl_xor_sync(0xffffffffu, v, off);
        if (c == 0) {
            float invN = 1.f / (float)N;
            float lc = g_sumRelu * invN;
            float mq = g_sumQ * invN;
            out[0] = lc + v * (1.f / (float)NUM_C) + mq * mq;
        }
    }

    // Reset for the next replay (all 1024 threads, after the reads above).
    __syncthreads();
    g_s1[c] = 0.f; g_s2[c] = 0.f; g_cnt[c] = 0.f;
    if (c == 0) { g_sumRelu = 0.f; g_sumQ = 0.f; }
}

// ---------------------------------------------------------------------------
extern "C" void kernel_launch(void* const* d_in, const int* in_sizes, int n_in,
                              void* d_out, int out_size)
{
    const float4* z4     = (const float4*)d_in[0];
    const void*   labels = d_in[1];
    const float4* J4     = (const float4*)d_in[2];
    const int N = in_sizes[1];

    // GB300: 152 SMs x 3 blocks/SM (launch_bounds 256,3) = 456 resident blocks.
    k_main<<<456, 256>>>(z4, labels, J4, N);

    // PDL launch of the finalize kernel: overlaps its launch latency with
    // k_main's tail; gridDependencySynchronize provides the ordering.
    cudaLaunchConfig_t cfg = {};
    cfg.gridDim  = dim3(1, 1, 1);
    cfg.blockDim = dim3(NUM_C, 1, 1);
    cfg.dynamicSmemBytes = 0;
    cfg.stream = 0;
    cudaLaunchAttribute attr[1];
    attr[0].id = cudaLaunchAttributeProgrammaticStreamSerialization;
    attr[0].val.programmaticStreamSerializationAllowed = 1;
    cfg.attrs = attr;
    cfg.numAttrs = 1;
    cudaLaunchKernelEx(&cfg, k_finalize, (float*)d_out, N);
}